// round 8
// baseline (speedup 1.0000x reference)
#include <cuda_runtime.h>

// Problem constants
#define DIMC   128
#define HEADS  8
#define HD     16
#define RESV   32
#define LTOK   (RESV*RESV*RESV)   // 32768
#define WINT   512                // 32*4*4 tokens per window
#define QSCALE (0.25f * 1.4426950408889634f)   // SCALE * log2(e): scores in log2 domain

// ---- packed f32x2 helpers (Blackwell FFMA2 path, PTX-only) ----
__device__ __forceinline__ unsigned long long pk2(float a, float b) {
    unsigned long long r;
    asm("mov.b64 %0, {%1,%2};" : "=l"(r) : "f"(a), "f"(b));
    return r;
}
__device__ __forceinline__ void upk2(unsigned long long v, float& a, float& b) {
    asm("mov.b64 {%0,%1}, %2;" : "=f"(a), "=f"(b) : "l"(v));
}
__device__ __forceinline__ unsigned long long ffma2(unsigned long long a,
                                                    unsigned long long b,
                                                    unsigned long long c) {
    unsigned long long d;
    asm("fma.rn.f32x2 %0, %1, %2, %3;" : "=l"(d) : "l"(a), "l"(b), "l"(c));
    return d;
}
__device__ __forceinline__ unsigned long long fmul2(unsigned long long a,
                                                    unsigned long long b) {
    unsigned long long d;
    asm("mul.rn.f32x2 %0, %1, %2;" : "=l"(d) : "l"(a), "l"(b));
    return d;
}
__device__ __forceinline__ unsigned long long fadd2(unsigned long long a,
                                                    unsigned long long b) {
    unsigned long long d;
    asm("add.rn.f32x2 %0, %1, %2;" : "=l"(d) : "l"(a), "l"(b));
    return d;
}
__device__ __forceinline__ float ex2f(float x) {
    float y;
    asm("ex2.approx.f32 %0, %1;" : "=f"(y) : "f"(x));
    return y;
}

// Shared memory layout (floats):
//   ks  [512*16]  K rows, row-major (broadcast reads in key loop)
//   vs  [512*16]  V rows, row-major (key loop broadcast + LePE float4 gather)
//   wsm [125*16]  depthwise conv weights for this head's channels, [tap][d]
//   bsm [16]      bias
#define SM_KS   0
#define SM_VS   8192
#define SM_W    16384
#define SM_B    (16384 + 2000)
#define SM_FLOATS (16384 + 2000 + 16)   // 18400 floats = 73600 bytes

__global__ void __launch_bounds__(128, 3)
lepe_attn_kernel(const float* __restrict__ qkv,
                 const float* __restrict__ wconv,
                 const float* __restrict__ bias,
                 float* __restrict__ out)
{
    extern __shared__ float smem[];
    float* ks  = smem + SM_KS;
    float* vs  = smem + SM_VS;
    float* wsm = smem + SM_W;
    float* bsm = smem + SM_B;

    const int t    = threadIdx.x;          // 0..127; owns tokens t+128*tk, tk=0..3
    const int wh   = blockIdx.x;           // 1024 = 128 windows * 8 heads
    const int head = wh & 7;
    const int win  = wh >> 3;
    const int b    = win >> 6;             // batch
    const int w_o  = (win >> 3) & 7;       // window coord along W
    const int s_o  = win & 7;              // window coord along S

    const int hi0 = t >> 4;                // 0..7 (token tk has hi0 + 8*tk)
    const int wi  = (t >> 2) & 3;
    const int si  = t & 3;
    const int l0  = hi0 * 1024 + (w_o * 4 + wi) * 32 + (s_o * 4 + si);

    const int MOFF  = 2 * LTOK * DIMC;                    // q/k/v matrix stride
    const int base0 = (b * LTOK + l0) * DIMC + head * HD;
    // token tk: hi += 8*tk  ->  l += 8192*tk  ->  base += 1048576*tk

    // ---- load K/V rows for all 4 tokens into smem; Q rows into regs ----
    unsigned long long q2[32];              // 4 queries x 8 packed pairs
#pragma unroll
    for (int tk = 0; tk < 4; ++tk) {
        const int tt = t + tk * 128;
        const int bb = base0 + tk * (8 * 1024 * DIMC);
        // K row
        {
            const float4* kg = (const float4*)(qkv + MOFF + bb);
            float4 a0 = kg[0], a1 = kg[1], a2 = kg[2], a3 = kg[3];
            float4* dst = (float4*)(ks + tt * 16);
            dst[0] = a0; dst[1] = a1; dst[2] = a2; dst[3] = a3;
        }
        // V row
        {
            const float4* vg = (const float4*)(qkv + 2 * MOFF + bb);
            float4 a0 = vg[0], a1 = vg[1], a2 = vg[2], a3 = vg[3];
            float4* dst = (float4*)(vs + tt * 16);
            dst[0] = a0; dst[1] = a1; dst[2] = a2; dst[3] = a3;
        }
        // Q row (pre-scaled by SCALE*log2e, packed)
        {
            const float4* qg = (const float4*)(qkv + bb);
            float4 a0 = qg[0], a1 = qg[1], a2 = qg[2], a3 = qg[3];
            q2[tk * 8 + 0] = pk2(a0.x * QSCALE, a0.y * QSCALE);
            q2[tk * 8 + 1] = pk2(a0.z * QSCALE, a0.w * QSCALE);
            q2[tk * 8 + 2] = pk2(a1.x * QSCALE, a1.y * QSCALE);
            q2[tk * 8 + 3] = pk2(a1.z * QSCALE, a1.w * QSCALE);
            q2[tk * 8 + 4] = pk2(a2.x * QSCALE, a2.y * QSCALE);
            q2[tk * 8 + 5] = pk2(a2.z * QSCALE, a2.w * QSCALE);
            q2[tk * 8 + 6] = pk2(a3.x * QSCALE, a3.y * QSCALE);
            q2[tk * 8 + 7] = pk2(a3.z * QSCALE, a3.w * QSCALE);
        }
    }
    // depthwise conv weights for this head's 16 channels: wsm[tap*16 + d]
    for (int i = t; i < 125 * 16; i += 128) {
        int tap = i >> 4, d = i & 15;
        wsm[i] = wconv[(head * HD + d) * 125 + tap];
    }
    if (t < 16) bsm[t] = bias[head * HD + t];

    __syncthreads();

    // ---- streaming attention: fused QK^T + softmax (no max tracking; scores
    //      ~N(0,1), exp2 safe in fp32) + PV. Four query chains per thread
    //      share every K/V smem read. K-phase / V-phase staging keeps peak
    //      register pressure under the 3-CTA cap (170). ----
    unsigned long long acc2[32];            // 4 queries x 8 packed pairs
#pragma unroll
    for (int i = 0; i < 32; ++i) acc2[i] = 0ull;
    float den0 = 0.f, den1 = 0.f, den2s = 0.f, den3 = 0.f;

    const ulonglong2* kp = (const ulonglong2*)ks;
    const ulonglong2* vp = (const ulonglong2*)vs;

#pragma unroll 2
    for (int key = 0; key < WINT; ++key) {
        // --- K phase: scores for 4 queries ---
        ulonglong2 a0 = kp[0];
        ulonglong2 a1 = kp[1];
        ulonglong2 a2 = kp[2];
        ulonglong2 a3 = kp[3];
        kp += 4;

        float p[4];
#pragma unroll
        for (int qi = 0; qi < 4; ++qi) {
            const unsigned long long* q = q2 + qi * 8;
            unsigned long long s0 = fmul2(q[0], a0.x);
            unsigned long long s1 = fmul2(q[1], a0.y);
            s0 = ffma2(q[2], a1.x, s0);
            s1 = ffma2(q[3], a1.y, s1);
            s0 = ffma2(q[4], a2.x, s0);
            s1 = ffma2(q[5], a2.y, s1);
            s0 = ffma2(q[6], a3.x, s0);
            s1 = ffma2(q[7], a3.y, s1);
            s0 = fadd2(s0, s1);
            float lo, hi2;
            upk2(s0, lo, hi2);
            p[qi] = ex2f(lo + hi2);         // scores already in log2 domain
        }
        den0 += p[0];
        den1 += p[1];
        den2s += p[2];
        den3 += p[3];

        // --- V phase: PV accumulate for 4 queries ---
        ulonglong2 b0 = vp[0];
        ulonglong2 b1 = vp[1];
        ulonglong2 b2 = vp[2];
        ulonglong2 b3 = vp[3];
        vp += 4;

#pragma unroll
        for (int qi = 0; qi < 4; ++qi) {
            unsigned long long pq = pk2(p[qi], p[qi]);
            unsigned long long* ac = acc2 + qi * 8;
            ac[0] = ffma2(pq, b0.x, ac[0]);
            ac[1] = ffma2(pq, b0.y, ac[1]);
            ac[2] = ffma2(pq, b1.x, ac[2]);
            ac[3] = ffma2(pq, b1.y, ac[3]);
            ac[4] = ffma2(pq, b2.x, ac[4]);
            ac[5] = ffma2(pq, b2.y, ac[5]);
            ac[6] = ffma2(pq, b3.x, ac[6]);
            ac[7] = ffma2(pq, b3.y, ac[7]);
        }
    }

    float den[4] = {den0, den1, den2s, den3};

    float res[4][16];
#pragma unroll
    for (int qi = 0; qi < 4; ++qi) {
        float inv = 1.0f / den[qi];
#pragma unroll
        for (int i = 0; i < 8; ++i) {
            float a, c;
            upk2(acc2[qi * 8 + i], a, c);
            res[qi][2 * i]     = a * inv;
            res[qi][2 * i + 1] = c * inv;
        }
    }

    // ---- LePE: depthwise 5x5x5 conv over (32,4,4) window, pad 2, + bias ----
#pragma unroll
    for (int tk = 0; tk < 4; ++tk) {
        float* r = res[tk];
        const int hi = hi0 + tk * 8;
#pragma unroll
        for (int d = 0; d < 16; ++d) r[d] += bsm[d];

        for (int dh = 0; dh < 5; ++dh) {
            int hs = hi + dh - 2;
            if ((unsigned)hs >= 32u) continue;
            for (int dw = 0; dw < 5; ++dw) {
                int wsp = wi + dw - 2;
                if ((unsigned)wsp >= 4u) continue;
                for (int ds = 0; ds < 5; ++ds) {
                    int ss = si + ds - 2;
                    if ((unsigned)ss >= 4u) continue;
                    int tsrc = hs * 16 + wsp * 4 + ss;
                    const float4* vrow = (const float4*)(vs + tsrc * 16);
                    const float4* wrow =
                        (const float4*)(wsm + ((dh * 5 + dw) * 5 + ds) * 16);
#pragma unroll
                    for (int j = 0; j < 4; ++j) {
                        float4 wv = wrow[j];
                        float4 vv = vrow[j];
                        r[4 * j + 0] += wv.x * vv.x;
                        r[4 * j + 1] += wv.y * vv.y;
                        r[4 * j + 2] += wv.z * vv.z;
                        r[4 * j + 3] += wv.w * vv.w;
                    }
                }
            }
        }
    }

    // ---- write outputs for all 4 tokens ----
#pragma unroll
    for (int tk = 0; tk < 4; ++tk) {
        const float* r = res[tk];
        float4* og = (float4*)(out + base0 + tk * (8 * 1024 * DIMC));
        og[0] = make_float4(r[0],  r[1],  r[2],  r[3]);
        og[1] = make_float4(r[4],  r[5],  r[6],  r[7]);
        og[2] = make_float4(r[8],  r[9],  r[10], r[11]);
        og[3] = make_float4(r[12], r[13], r[14], r[15]);
    }
}

extern "C" void kernel_launch(void* const* d_in, const int* in_sizes, int n_in,
                              void* d_out, int out_size)
{
    (void)in_sizes; (void)n_in; (void)out_size;
    const float* qkv  = (const float*)d_in[0];
    const float* w    = (const float*)d_in[1];
    const float* bias = (const float*)d_in[2];
    float* out = (float*)d_out;

    const size_t smem_bytes = SM_FLOATS * sizeof(float);   // 73600 B
    cudaFuncSetAttribute(lepe_attn_kernel,
                         cudaFuncAttributeMaxDynamicSharedMemorySize,
                         (int)smem_bytes);

    // 128 windows * 8 heads = 1024 blocks; 128 threads, 4 queries per thread
    lepe_attn_kernel<<<1024, 128, smem_bytes>>>(qkv, w, bias, out);
}

// round 9
// speedup vs baseline: 1.0004x; 1.0004x over previous
#include <cuda_runtime.h>

// Problem constants
#define DIMC   128
#define HEADS  8
#define HD     16
#define RESV   32
#define LTOK   (RESV*RESV*RESV)   // 32768
#define WINT   512                // 32*4*4 tokens per window
#define QSCALE (0.25f * 1.4426950408889634f)   // SCALE * log2(e): scores in log2 domain

// ---- packed f32x2 helpers (Blackwell FFMA2 path, PTX-only) ----
__device__ __forceinline__ unsigned long long pk2(float a, float b) {
    unsigned long long r;
    asm("mov.b64 %0, {%1,%2};" : "=l"(r) : "f"(a), "f"(b));
    return r;
}
__device__ __forceinline__ void upk2(unsigned long long v, float& a, float& b) {
    asm("mov.b64 {%0,%1}, %2;" : "=f"(a), "=f"(b) : "l"(v));
}
__device__ __forceinline__ unsigned long long ffma2(unsigned long long a,
                                                    unsigned long long b,
                                                    unsigned long long c) {
    unsigned long long d;
    asm("fma.rn.f32x2 %0, %1, %2, %3;" : "=l"(d) : "l"(a), "l"(b), "l"(c));
    return d;
}
__device__ __forceinline__ unsigned long long fmul2(unsigned long long a,
                                                    unsigned long long b) {
    unsigned long long d;
    asm("mul.rn.f32x2 %0, %1, %2;" : "=l"(d) : "l"(a), "l"(b));
    return d;
}
__device__ __forceinline__ unsigned long long fadd2(unsigned long long a,
                                                    unsigned long long b) {
    unsigned long long d;
    asm("add.rn.f32x2 %0, %1, %2;" : "=l"(d) : "l"(a), "l"(b));
    return d;
}
__device__ __forceinline__ float ex2f(float x) {
    float y;
    asm("ex2.approx.f32 %0, %1;" : "=f"(y) : "f"(x));
    return y;
}

// Shared memory layout (floats):
//   ks  [512*16]  K rows, row-major (broadcast reads in key loop)
//   vs  [512*16]  V rows, row-major (key loop broadcast + LePE float4 gather)
//   wsm [125*16]  depthwise conv weights for this head's channels, [tap][d]
//   bsm [16]      bias
#define SM_KS   0
#define SM_VS   8192
#define SM_W    16384
#define SM_B    (16384 + 2000)
#define SM_FLOATS (16384 + 2000 + 16)   // 18400 floats = 73600 bytes

__global__ void __launch_bounds__(128, 3)
lepe_attn_kernel(const float* __restrict__ qkv,
                 const float* __restrict__ wconv,
                 const float* __restrict__ bias,
                 float* __restrict__ out)
{
    extern __shared__ float smem[];
    float* ks  = smem + SM_KS;
    float* vs  = smem + SM_VS;
    float* wsm = smem + SM_W;
    float* bsm = smem + SM_B;

    const int t    = threadIdx.x;          // 0..127; owns tokens t+128*tk, tk=0..3
    const int wh   = blockIdx.x;           // 1024 = 128 windows * 8 heads
    const int head = wh & 7;
    const int win  = wh >> 3;
    const int b    = win >> 6;             // batch
    const int w_o  = (win >> 3) & 7;       // window coord along W
    const int s_o  = win & 7;              // window coord along S

    const int hi0 = t >> 4;                // 0..7 (token tk has hi0 + 8*tk)
    const int wi  = (t >> 2) & 3;
    const int si  = t & 3;
    const int l0  = hi0 * 1024 + (w_o * 4 + wi) * 32 + (s_o * 4 + si);

    const int MOFF  = 2 * LTOK * DIMC;                    // q/k/v matrix stride
    const int base0 = (b * LTOK + l0) * DIMC + head * HD;
    // token tk: hi += 8*tk  ->  l += 8192*tk  ->  base += 1048576*tk

    // ---- load K/V rows for all 4 tokens into smem; Q rows into regs ----
    unsigned long long q2[32];              // 4 queries x 8 packed pairs
#pragma unroll
    for (int tk = 0; tk < 4; ++tk) {
        const int tt = t + tk * 128;
        const int bb = base0 + tk * (8 * 1024 * DIMC);
        // K row
        {
            const float4* kg = (const float4*)(qkv + MOFF + bb);
            float4 a0 = kg[0], a1 = kg[1], a2 = kg[2], a3 = kg[3];
            float4* dst = (float4*)(ks + tt * 16);
            dst[0] = a0; dst[1] = a1; dst[2] = a2; dst[3] = a3;
        }
        // V row
        {
            const float4* vg = (const float4*)(qkv + 2 * MOFF + bb);
            float4 a0 = vg[0], a1 = vg[1], a2 = vg[2], a3 = vg[3];
            float4* dst = (float4*)(vs + tt * 16);
            dst[0] = a0; dst[1] = a1; dst[2] = a2; dst[3] = a3;
        }
        // Q row (pre-scaled by SCALE*log2e, packed)
        {
            const float4* qg = (const float4*)(qkv + bb);
            float4 a0 = qg[0], a1 = qg[1], a2 = qg[2], a3 = qg[3];
            q2[tk * 8 + 0] = pk2(a0.x * QSCALE, a0.y * QSCALE);
            q2[tk * 8 + 1] = pk2(a0.z * QSCALE, a0.w * QSCALE);
            q2[tk * 8 + 2] = pk2(a1.x * QSCALE, a1.y * QSCALE);
            q2[tk * 8 + 3] = pk2(a1.z * QSCALE, a1.w * QSCALE);
            q2[tk * 8 + 4] = pk2(a2.x * QSCALE, a2.y * QSCALE);
            q2[tk * 8 + 5] = pk2(a2.z * QSCALE, a2.w * QSCALE);
            q2[tk * 8 + 6] = pk2(a3.x * QSCALE, a3.y * QSCALE);
            q2[tk * 8 + 7] = pk2(a3.z * QSCALE, a3.w * QSCALE);
        }
    }
    // depthwise conv weights for this head's 16 channels: wsm[tap*16 + d]
    for (int i = t; i < 125 * 16; i += 128) {
        int tap = i >> 4, d = i & 15;
        wsm[i] = wconv[(head * HD + d) * 125 + tap];
    }
    if (t < 16) bsm[t] = bias[head * HD + t];

    __syncthreads();

    // ---- streaming attention: fused QK^T + softmax (no max tracking; scores
    //      ~N(0,1), exp2 safe in fp32) + PV. Four query chains per thread
    //      share every K/V smem read. K-phase / V-phase staging keeps peak
    //      register pressure under the 3-CTA cap (170). ----
    unsigned long long acc2[32];            // 4 queries x 8 packed pairs
#pragma unroll
    for (int i = 0; i < 32; ++i) acc2[i] = 0ull;
    float den0 = 0.f, den1 = 0.f, den2s = 0.f, den3 = 0.f;

    const ulonglong2* kp = (const ulonglong2*)ks;
    const ulonglong2* vp = (const ulonglong2*)vs;

#pragma unroll 2
    for (int key = 0; key < WINT; ++key) {
        // --- K phase: scores for 4 queries ---
        ulonglong2 a0 = kp[0];
        ulonglong2 a1 = kp[1];
        ulonglong2 a2 = kp[2];
        ulonglong2 a3 = kp[3];
        kp += 4;

        float p[4];
#pragma unroll
        for (int qi = 0; qi < 4; ++qi) {
            const unsigned long long* q = q2 + qi * 8;
            unsigned long long s0 = fmul2(q[0], a0.x);
            unsigned long long s1 = fmul2(q[1], a0.y);
            s0 = ffma2(q[2], a1.x, s0);
            s1 = ffma2(q[3], a1.y, s1);
            s0 = ffma2(q[4], a2.x, s0);
            s1 = ffma2(q[5], a2.y, s1);
            s0 = ffma2(q[6], a3.x, s0);
            s1 = ffma2(q[7], a3.y, s1);
            s0 = fadd2(s0, s1);
            float lo, hi2;
            upk2(s0, lo, hi2);
            p[qi] = ex2f(lo + hi2);         // scores already in log2 domain
        }
        den0 += p[0];
        den1 += p[1];
        den2s += p[2];
        den3 += p[3];

        // --- V phase: PV accumulate for 4 queries ---
        ulonglong2 b0 = vp[0];
        ulonglong2 b1 = vp[1];
        ulonglong2 b2 = vp[2];
        ulonglong2 b3 = vp[3];
        vp += 4;

#pragma unroll
        for (int qi = 0; qi < 4; ++qi) {
            unsigned long long pq = pk2(p[qi], p[qi]);
            unsigned long long* ac = acc2 + qi * 8;
            ac[0] = ffma2(pq, b0.x, ac[0]);
            ac[1] = ffma2(pq, b0.y, ac[1]);
            ac[2] = ffma2(pq, b1.x, ac[2]);
            ac[3] = ffma2(pq, b1.y, ac[3]);
            ac[4] = ffma2(pq, b2.x, ac[4]);
            ac[5] = ffma2(pq, b2.y, ac[5]);
            ac[6] = ffma2(pq, b3.x, ac[6]);
            ac[7] = ffma2(pq, b3.y, ac[7]);
        }
    }

    float den[4] = {den0, den1, den2s, den3};

    float res[4][16];
#pragma unroll
    for (int qi = 0; qi < 4; ++qi) {
        float inv = 1.0f / den[qi];
#pragma unroll
        for (int i = 0; i < 8; ++i) {
            float a, c;
            upk2(acc2[qi * 8 + i], a, c);
            res[qi][2 * i]     = a * inv;
            res[qi][2 * i + 1] = c * inv;
        }
    }

    // ---- LePE: depthwise 5x5x5 conv over (32,4,4) window, pad 2, + bias ----
#pragma unroll
    for (int tk = 0; tk < 4; ++tk) {
        float* r = res[tk];
        const int hi = hi0 + tk * 8;
#pragma unroll
        for (int d = 0; d < 16; ++d) r[d] += bsm[d];

        for (int dh = 0; dh < 5; ++dh) {
            int hs = hi + dh - 2;
            if ((unsigned)hs >= 32u) continue;
            for (int dw = 0; dw < 5; ++dw) {
                int wsp = wi + dw - 2;
                if ((unsigned)wsp >= 4u) continue;
                for (int ds = 0; ds < 5; ++ds) {
                    int ss = si + ds - 2;
                    if ((unsigned)ss >= 4u) continue;
                    int tsrc = hs * 16 + wsp * 4 + ss;
                    const float4* vrow = (const float4*)(vs + tsrc * 16);
                    const float4* wrow =
                        (const float4*)(wsm + ((dh * 5 + dw) * 5 + ds) * 16);
#pragma unroll
                    for (int j = 0; j < 4; ++j) {
                        float4 wv = wrow[j];
                        float4 vv = vrow[j];
                        r[4 * j + 0] += wv.x * vv.x;
                        r[4 * j + 1] += wv.y * vv.y;
                        r[4 * j + 2] += wv.z * vv.z;
                        r[4 * j + 3] += wv.w * vv.w;
                    }
                }
            }
        }
    }

    // ---- write outputs for all 4 tokens ----
#pragma unroll
    for (int tk = 0; tk < 4; ++tk) {
        const float* r = res[tk];
        float4* og = (float4*)(out + base0 + tk * (8 * 1024 * DIMC));
        og[0] = make_float4(r[0],  r[1],  r[2],  r[3]);
        og[1] = make_float4(r[4],  r[5],  r[6],  r[7]);
        og[2] = make_float4(r[8],  r[9],  r[10], r[11]);
        og[3] = make_float4(r[12], r[13], r[14], r[15]);
    }
}

extern "C" void kernel_launch(void* const* d_in, const int* in_sizes, int n_in,
                              void* d_out, int out_size)
{
    (void)in_sizes; (void)n_in; (void)out_size;
    const float* qkv  = (const float*)d_in[0];
    const float* w    = (const float*)d_in[1];
    const float* bias = (const float*)d_in[2];
    float* out = (float*)d_out;

    const size_t smem_bytes = SM_FLOATS * sizeof(float);   // 73600 B
    cudaFuncSetAttribute(lepe_attn_kernel,
                         cudaFuncAttributeMaxDynamicSharedMemorySize,
                         (int)smem_bytes);

    // 128 windows * 8 heads = 1024 blocks; 128 threads, 4 queries per thread
    lepe_attn_kernel<<<1024, 128, smem_bytes>>>(qkv, w, bias, out);
}

// round 11
// speedup vs baseline: 2.3702x; 2.3691x over previous
#include <cuda_runtime.h>
#include <cuda_bf16.h>
#include <cstdint>

#define DIMC   128
#define LTOK   32768
#define QSCALE (0.25f * 1.4426950408889634f)   // HD^-0.5 * log2(e)

// ---------------- smem byte offsets ----------------
// Qh/Ql, Kh/Kl: 512 rows x 24 bf16 (48B stride; 16 used) -- conflict-free frag loads
// VTh/VTl: V^T [16 d][520 keys] bf16 (1040B stride; 512 used)
// wsm: conv weights [16 c][125 taps] fp32
// cbuf: conv output+bias [512 tokens][20 floats] (16 used)
#define SM_QH   0
#define SM_QL   24576
#define SM_KH   49152
#define SM_KL   73728
#define SM_VTH  98304
#define SM_VTL  114944
#define SM_WSM  131584
#define SM_CBUF 139584
#define SMEM_TOTAL 180544

// ---------------- helpers ----------------
__device__ __forceinline__ float ex2f(float x) {
    float y; asm("ex2.approx.f32 %0, %1;" : "=f"(y) : "f"(x)); return y;
}
// pack: low 16 bits = bf16(a), high 16 bits = bf16(b)
__device__ __forceinline__ uint32_t pkbf2(float a, float b) {
    uint32_t r;
    asm("cvt.rn.satfinite.bf16x2.f32 %0, %1, %2;" : "=r"(r) : "f"(b), "f"(a));
    return r;
}
// m16n8k16 row.col bf16 MMA, fp32 accumulate in-place
__device__ __forceinline__ void mma16816(float* c, const uint32_t* a,
                                          uint32_t b0, uint32_t b1) {
    asm volatile(
        "mma.sync.aligned.m16n8k16.row.col.f32.bf16.bf16.f32 "
        "{%0,%1,%2,%3}, {%4,%5,%6,%7}, {%8,%9}, {%0,%1,%2,%3};"
        : "+f"(c[0]), "+f"(c[1]), "+f"(c[2]), "+f"(c[3])
        : "r"(a[0]), "r"(a[1]), "r"(a[2]), "r"(a[3]), "r"(b0), "r"(b1));
}
// split fp32 pair -> hi/lo bf16x2, store into padded row (48B stride)
__device__ __forceinline__ void split_store(char* hib, char* lob, int row, int i,
                                            float a, float b) {
    uint32_t hp = pkbf2(a, b);
    float r0 = a - __uint_as_float(hp << 16);
    float r1 = b - __uint_as_float(hp & 0xFFFF0000u);
    uint32_t lp = pkbf2(r0, r1);
    *(uint32_t*)(hib + row * 48 + i * 4) = hp;
    *(uint32_t*)(lob + row * 48 + i * 4) = lp;
}

// =============================== kernel ====================================
__global__ void __launch_bounds__(256, 1)
lepe_attn_hmma(const float* __restrict__ qkv,
               const float* __restrict__ wconv,
               const float* __restrict__ bias,
               float* __restrict__ out)
{
    extern __shared__ char sm[];
    float* wsm  = (float*)(sm + SM_WSM);
    float* cbuf = (float*)(sm + SM_CBUF);

    const int tid    = threadIdx.x;
    const int warpid = tid >> 5;
    const int lane   = tid & 31;

    const int wh   = blockIdx.x;          // 1024 = 128 windows * 8 heads
    const int head = wh & 7;
    const int win  = wh >> 3;
    const int b    = win >> 6;
    const int w_o  = (win >> 3) & 7;
    const int s_o  = win & 7;
    const int MOFF = 2 * LTOK * DIMC;

    // ================= prologue: convert Q/K/V to split-bf16 =================
#pragma unroll
    for (int tk = 0; tk < 2; ++tk) {
        const int tt = tid + tk * 256;                 // token 0..511
        const int hi = tt >> 4, wi = (tt >> 2) & 3, si = tt & 3;
        const int l  = hi * 1024 + (w_o * 4 + wi) * 32 + s_o * 4 + si;
        const int gb = (b * LTOK + l) * DIMC + head * 16;

        const float4* qg = (const float4*)(qkv + gb);
        const float4* kg = (const float4*)(qkv + MOFF + gb);
        const float4* vg = (const float4*)(qkv + 2 * MOFF + gb);
        float4 q4[4] = {qg[0], qg[1], qg[2], qg[3]};
        float4 k4[4] = {kg[0], kg[1], kg[2], kg[3]};
        float4 v4[4] = {vg[0], vg[1], vg[2], vg[3]};

#pragma unroll
        for (int i = 0; i < 4; ++i) {
            split_store(sm + SM_QH, sm + SM_QL, tt, 2*i,
                        q4[i].x * QSCALE, q4[i].y * QSCALE);
            split_store(sm + SM_QH, sm + SM_QL, tt, 2*i+1,
                        q4[i].z * QSCALE, q4[i].w * QSCALE);
            split_store(sm + SM_KH, sm + SM_KL, tt, 2*i,   k4[i].x, k4[i].y);
            split_store(sm + SM_KH, sm + SM_KL, tt, 2*i+1, k4[i].z, k4[i].w);
        }
        float vv[16] = {v4[0].x,v4[0].y,v4[0].z,v4[0].w, v4[1].x,v4[1].y,v4[1].z,v4[1].w,
                        v4[2].x,v4[2].y,v4[2].z,v4[2].w, v4[3].x,v4[3].y,v4[3].z,v4[3].w};
#pragma unroll
        for (int d = 0; d < 16; ++d) {
            uint32_t hb = pkbf2(vv[d], 0.f) & 0xFFFFu;
            float lo = vv[d] - __uint_as_float(hb << 16);
            uint32_t lb = pkbf2(lo, 0.f) & 0xFFFFu;
            *(unsigned short*)(sm + SM_VTH + d * 1040 + tt * 2) = (unsigned short)hb;
            *(unsigned short*)(sm + SM_VTL + d * 1040 + tt * 2) = (unsigned short)lb;
        }
    }
    // conv weights
    for (int i = tid; i < 16 * 125; i += 256) {
        int c = i / 125, tap = i % 125;
        wsm[i] = wconv[(head * 16 + c) * 125 + tap];
    }
    __syncthreads();

    // ================= LePE conv (registers + shuffles) =================
    // lane = H row (0..31); warp handles channels {2*warpid, 2*warpid+1}
    {
        float vr[2][16], co[2][16], bv[2];
#pragma unroll
        for (int c2 = 0; c2 < 2; ++c2) {
            int c  = warpid * 2 + c2;
            bv[c2] = __ldg(bias + head * 16 + c);
            int gb = (b * LTOK + lane * 1024 + (w_o * 4) * 32 + s_o * 4) * DIMC
                   + head * 16 + c;
#pragma unroll
            for (int j = 0; j < 16; ++j) {
                vr[c2][j] = __ldg(qkv + 2 * MOFF + gb + ((j >> 2) * 32 + (j & 3)) * DIMC);
                co[c2][j] = 0.f;
            }
        }
#pragma unroll
        for (int dh = 0; dh < 5; ++dh) {
            int hs = lane + dh - 2;
            bool ok = (unsigned)hs < 32u;
            int src = hs < 0 ? 0 : (hs > 31 ? 31 : hs);
            float tmp[2][16];
#pragma unroll
            for (int c2 = 0; c2 < 2; ++c2)
#pragma unroll
                for (int j = 0; j < 16; ++j)
                    tmp[c2][j] = __shfl_sync(0xFFFFFFFFu, vr[c2][j], src);
            if (ok) {
#pragma unroll
                for (int c2 = 0; c2 < 2; ++c2) {
                    const float* wc = wsm + (warpid * 2 + c2) * 125 + dh * 25;
#pragma unroll
                    for (int dw = 0; dw < 5; ++dw)
#pragma unroll
                        for (int ds = 0; ds < 5; ++ds) {
                            float wt = wc[dw * 5 + ds];
#pragma unroll
                            for (int w = 0; w < 4; ++w)
#pragma unroll
                                for (int s = 0; s < 4; ++s) {
                                    int ww = w + dw - 2, ss = s + ds - 2;
                                    if (ww >= 0 && ww < 4 && ss >= 0 && ss < 4)
                                        co[c2][w * 4 + s] += wt * tmp[c2][ww * 4 + ss];
                                }
                        }
                }
            }
        }
#pragma unroll
        for (int c2 = 0; c2 < 2; ++c2)
#pragma unroll
            for (int j = 0; j < 16; ++j)
                cbuf[(lane * 16 + j) * 20 + warpid * 2 + c2] = co[c2][j] + bv[c2];
    }
    __syncthreads();

    // ================= attention: per-warp 64 q-rows, flash loop =============
    // Q A-fragments (4 m-tiles x hi/lo)
    uint32_t qh[4][4], ql[4][4];
#pragma unroll
    for (int mt = 0; mt < 4; ++mt) {
        int r0 = warpid * 64 + mt * 16 + (lane >> 2);
        const char* qro = sm + SM_QH + r0 * 48 + (lane & 3) * 4;
        qh[mt][0] = *(const uint32_t*)qro;
        qh[mt][1] = *(const uint32_t*)(qro + 8 * 48);
        qh[mt][2] = *(const uint32_t*)(qro + 16);
        qh[mt][3] = *(const uint32_t*)(qro + 8 * 48 + 16);
        const char* qrl = sm + SM_QL + r0 * 48 + (lane & 3) * 4;
        ql[mt][0] = *(const uint32_t*)qrl;
        ql[mt][1] = *(const uint32_t*)(qrl + 8 * 48);
        ql[mt][2] = *(const uint32_t*)(qrl + 16);
        ql[mt][3] = *(const uint32_t*)(qrl + 8 * 48 + 16);
    }

    float o[4][2][4];
    float den[4][2];
#pragma unroll
    for (int mt = 0; mt < 4; ++mt) {
        den[mt][0] = den[mt][1] = 0.f;
#pragma unroll
        for (int nt = 0; nt < 2; ++nt)
#pragma unroll
            for (int j = 0; j < 4; ++j) o[mt][nt][j] = 0.f;
    }

#pragma unroll 1
    for (int ch = 0; ch < 32; ++ch) {
        uint32_t pah[4][4], pal[4][4];
        // ---- S phase: scores for 16 keys, exp2, split-bf16 P frags ----
#pragma unroll
        for (int nt = 0; nt < 2; ++nt) {
            int krow = ch * 16 + nt * 8 + (lane >> 2);
            const char* kro = sm + SM_KH + krow * 48 + (lane & 3) * 4;
            uint32_t kh0 = *(const uint32_t*)kro;
            uint32_t kh1 = *(const uint32_t*)(kro + 16);
            const char* krl = sm + SM_KL + krow * 48 + (lane & 3) * 4;
            uint32_t kl0 = *(const uint32_t*)krl;
            uint32_t kl1 = *(const uint32_t*)(krl + 16);
#pragma unroll
            for (int mt = 0; mt < 4; ++mt) {
                float s[4] = {0.f, 0.f, 0.f, 0.f};
                mma16816(s, qh[mt], kh0, kh1);
                mma16816(s, qh[mt], kl0, kl1);
                mma16816(s, ql[mt], kh0, kh1);
                float p0 = ex2f(s[0]), p1 = ex2f(s[1]);
                float p2 = ex2f(s[2]), p3 = ex2f(s[3]);
                den[mt][0] += p0 + p1;
                den[mt][1] += p2 + p3;
                uint32_t h01 = pkbf2(p0, p1), h23 = pkbf2(p2, p3);
                uint32_t l01 = pkbf2(p0 - __uint_as_float(h01 << 16),
                                     p1 - __uint_as_float(h01 & 0xFFFF0000u));
                uint32_t l23 = pkbf2(p2 - __uint_as_float(h23 << 16),
                                     p3 - __uint_as_float(h23 & 0xFFFF0000u));
                pah[mt][nt * 2 + 0] = h01;
                pah[mt][nt * 2 + 1] = h23;
                pal[mt][nt * 2 + 0] = l01;
                pal[mt][nt * 2 + 1] = l23;
            }
        }
        // ---- PV phase ----
#pragma unroll
        for (int ntd = 0; ntd < 2; ++ntd) {
            int vrow = ntd * 8 + (lane >> 2);
            int kof  = ch * 16 + (lane & 3) * 2;
            const char* vh = sm + SM_VTH + vrow * 1040 + kof * 2;
            uint32_t vh0 = *(const uint32_t*)vh;
            uint32_t vh1 = *(const uint32_t*)(vh + 16);
            const char* vl = sm + SM_VTL + vrow * 1040 + kof * 2;
            uint32_t vl0 = *(const uint32_t*)vl;
            uint32_t vl1 = *(const uint32_t*)(vl + 16);
#pragma unroll
            for (int mt = 0; mt < 4; ++mt) {
                mma16816(o[mt][ntd], pah[mt], vh0, vh1);
                mma16816(o[mt][ntd], pal[mt], vh0, vh1);
                mma16816(o[mt][ntd], pah[mt], vl0, vl1);
            }
        }
    }

    // ================= output: normalize + conv + store =================
#pragma unroll
    for (int mt = 0; mt < 4; ++mt) {
#pragma unroll
        for (int rh = 0; rh < 2; ++rh) {
            float d = den[mt][rh];
            d += __shfl_xor_sync(0xFFFFFFFFu, d, 1);
            d += __shfl_xor_sync(0xFFFFFFFFu, d, 2);
            den[mt][rh] = d;
        }
#pragma unroll
        for (int rh = 0; rh < 2; ++rh) {
            int t = warpid * 64 + mt * 16 + (lane >> 2) + rh * 8;
            float inv = 1.0f / den[mt][rh];
            int hi = t >> 4, wi = (t >> 2) & 3, si = t & 3;
            int l  = hi * 1024 + (w_o * 4 + wi) * 32 + s_o * 4 + si;
            float* og = out + (size_t)(b * LTOK + l) * DIMC + head * 16;
#pragma unroll
            for (int ntd = 0; ntd < 2; ++ntd) {
                int dcol = ntd * 8 + (lane & 3) * 2;
                float c0 = o[mt][ntd][rh * 2 + 0] * inv + cbuf[t * 20 + dcol];
                float c1 = o[mt][ntd][rh * 2 + 1] * inv + cbuf[t * 20 + dcol + 1];
                *(float2*)(og + dcol) = make_float2(c0, c1);
            }
        }
    }
}

extern "C" void kernel_launch(void* const* d_in, const int* in_sizes, int n_in,
                              void* d_out, int out_size)
{
    (void)in_sizes; (void)n_in; (void)out_size;
    const float* qkv  = (const float*)d_in[0];
    const float* w    = (const float*)d_in[1];
    const float* bias = (const float*)d_in[2];
    float* out = (float*)d_out;

    cudaFuncSetAttribute(lepe_attn_hmma,
                         cudaFuncAttributeMaxDynamicSharedMemorySize, SMEM_TOTAL);
    lepe_attn_hmma<<<1024, 256, SMEM_TOTAL>>>(qkv, w, bias, out);
}